// round 14
// baseline (speedup 1.0000x reference)
#include <cuda_runtime.h>
#include <math.h>
#include <stdint.h>

// ================= scratch (device globals; no allocations) =================
__device__ float g_xz[(size_t)64 * 4096 * 256];     // input-conv gates fp32 (268 MB)
__device__ float g_xp[(size_t)64 * 16384 * 32];     // x tf32, k-interleaved (134 MB)
__device__ float g_hp0[(size_t)4 * 4096 * 64];      // h tf32 k-interleaved
__device__ float g_hp1[(size_t)4 * 4096 * 64];
__device__ float g_c  [(size_t)4 * 4096 * 64];
__device__ float g_Wt[(size_t)9  * 256 * 32];       // W tf32 chunk-major interleaved
__device__ float g_Ut[(size_t)18 * 256 * 32];

// ================= helpers ==================================================
__device__ __forceinline__ uint32_t f2tf32(float x) {
    uint32_t y;
    asm("cvt.rna.tf32.f32 %0, %1;" : "=r"(y) : "f"(x));
    return y;
}
__device__ __forceinline__ uint32_t smem_u32(const void* p) {
    uint32_t a;
    asm("{ .reg .u64 t; cvta.to.shared.u64 t, %1; cvt.u32.u64 %0, t; }" : "=r"(a) : "l"(p));
    return a;
}
__device__ __forceinline__ void mma_tf32(float* d, const uint32_t* a, const uint32_t* b) {
    asm volatile("mma.sync.aligned.m16n8k8.row.col.f32.tf32.tf32.f32 "
                 "{%0,%1,%2,%3}, {%4,%5,%6,%7}, {%8,%9}, {%0,%1,%2,%3};"
                 : "+f"(d[0]), "+f"(d[1]), "+f"(d[2]), "+f"(d[3])
                 : "r"(a[0]), "r"(a[1]), "r"(a[2]), "r"(a[3]),
                   "r"(b[0]), "r"(b[1]));
}
#define CP_ASYNC(dst, src, sz) \
    asm volatile("cp.async.ca.shared.global [%0], [%1], 16, %2;" \
                 :: "r"(dst), "l"(src), "r"(sz) : "memory")
#define CP_COMMIT()  asm volatile("cp.async.commit_group;" ::: "memory")
#define CP_WAIT_1()  asm volatile("cp.async.wait_group 1;" ::: "memory")
#define CP_WAIT_0()  asm volatile("cp.async.wait_group 0;" ::: "memory")

__device__ __forceinline__ float hsig(float x) {
    return fminf(fmaxf(0.2f * x + 0.5f, 0.f), 1.f);
}

// k-interleave: position p in octet holds source k = (p&1)*4 + (p>>1)
__device__ __forceinline__ int perm_src(int pos) {        // pos in [0,32)
    return (pos & ~7) + ((pos & 1) * 4) + ((pos & 7) >> 1);
}
__device__ __forceinline__ int perm_dst(int f) {          // inverse, f in [0,64)
    return (f & ~7) + ((f & 3) * 2) + ((f >> 2) & 1);
}

// smem: 2 stages of 10240 floats (A 64x32 @+0, B 256x32 @+2048 floats)
static constexpr uint32_t STAGE_FLOATS = 10240;
static constexpr uint32_t SMEM_BYTES = 2u * STAGE_FLOATS * 4u;   // 81920 B

// ================= prep kernels =============================================
__global__ void zero_state_kernel(float* __restrict__ h, float* __restrict__ c, int n) {
    int i = blockIdx.x * blockDim.x + threadIdx.x;
    if (i < n) { h[i] = 0.f; c[i] = 0.f; }
}

__global__ void convert_x_kernel(const float* __restrict__ x, float* __restrict__ xp, int total) {
    int idx = blockIdx.x * blockDim.x + threadIdx.x;
    if (idx >= total) return;
    int pix = idx >> 5, pos = idx & 31;
    xp[idx] = __uint_as_float(f2tf32(x[pix * 32 + perm_src(pos)]));
}

// Wt2[ch][co][pos] = tf32(Wsrc[(ch*32 + perm_src(pos))*256 + co])
__global__ void transpose_w_kernel(const float* __restrict__ Wsrc, float* __restrict__ Wt2, int total) {
    int idx = blockIdx.x * blockDim.x + threadIdx.x;
    if (idx >= total) return;
    int ch = idx >> 13;
    int r  = idx & 8191;
    int co = r >> 5, pos = r & 31;
    Wt2[idx] = __uint_as_float(f2tf32(Wsrc[(ch * 32 + perm_src(pos)) * 256 + co]));
}

// ================= cp.async implicit-GEMM conv (+ fused LSTM) ===============
// BM=64, BN=256, BK=32; 256 threads = 8 warps (2m x 4n), warp tile 32x64.
// __launch_bounds__(256,2) -> 2 CTAs/SM for cross-CTA phase overlap.
template<int STRIDE, int PAD, int CIN, int HIN, int HOUT, bool FUSED>
__global__ void __launch_bounds__(256, 2)
conv_mma(const float* __restrict__ X, const float* __restrict__ Wt2,
         float* __restrict__ Z, int tstep,
         const float* __restrict__ xz,
         const float* __restrict__ bias, const float* __restrict__ gamma,
         const float* __restrict__ beta, const float* __restrict__ mmean,
         const float* __restrict__ mvar,
         float* __restrict__ hp_out, float* __restrict__ cbuf,
         float* __restrict__ out) {
    extern __shared__ float smem[];
    __shared__ float s_bias[256], s_scale[64], s_beta[64], s_mm[64];

    const int t = threadIdx.x;
    if (FUSED) {
        s_bias[t] = bias[t];
        if (t < 64) {
            s_scale[t] = gamma[t] * rsqrtf(mvar[t] + 1e-3f);
            s_beta[t]  = beta[t];
            s_mm[t]    = mmean[t];
        }
    }

    const int wid = t >> 5, lane = t & 31;
    const int gid = lane >> 2, tg = lane & 3;
    const int wm = wid >> 2, wn = wid & 3;       // warp grid 2(m) x 4(n)
    const int mBase = blockIdx.x * 64;
    constexpr int NCH = 9 * CIN / 32;

    // ---- cp.async geometry (fixed per thread)
    const int gq = t & 7;                        // 16B quad within 32-float row
    const int r0A = t >> 3;                      // A rows r0A and r0A+32
    int nimg[2], oyv[2], oxv[2];
#pragma unroll
    for (int k = 0; k < 2; k++) {
        const int m = mBase + r0A + k * 32;
        nimg[k] = m / (HOUT * HOUT);
        const int rem = m % (HOUT * HOUT);
        oyv[k] = rem / HOUT; oxv[k] = rem % HOUT;
    }
    const uint32_t sbase = smem_u32(smem);
    uint32_t aDst[2], bDst[8];
#pragma unroll
    for (int k = 0; k < 2; k++) {
        const int r = r0A + k * 32;
        aDst[k] = sbase + r * 128 + ((gq ^ (r & 7)) << 4);
    }
#pragma unroll
    for (int k = 0; k < 8; k++) {
        const int co = (t >> 3) + k * 32;
        bDst[k] = sbase + 8192 + co * 128 + ((gq ^ (co & 7)) << 4);
    }

    auto issue = [&](int c, int s) {
        const int tap   = (c * 32) / CIN;
        const int ciOff = (c * 32) % CIN;
        const int ky = tap / 3, kx = tap % 3;
        const uint32_t so = (uint32_t)s * (STAGE_FLOATS * 4u);
#pragma unroll
        for (int k = 0; k < 2; k++) {
            const int iy = oyv[k] * STRIDE + ky - PAD;
            const int ix = oxv[k] * STRIDE + kx - PAD;
            const bool ok = (iy >= 0) & (iy < HIN) & (ix >= 0) & (ix < HIN);
            const float* src = ok
                ? X + (((size_t)nimg[k] * HIN + iy) * HIN + ix) * CIN + ciOff + gq * 4
                : X;
            CP_ASYNC(aDst[k] + so, src, ok ? 16 : 0);
        }
        const float* bsrc = Wt2 + (size_t)c * 8192 + (t >> 3) * 32 + gq * 4;
#pragma unroll
        for (int k = 0; k < 8; k++)
            CP_ASYNC(bDst[k] + so, bsrc + k * 1024, 16);
        CP_COMMIT();
    };

    float d[2][8][4];
#pragma unroll
    for (int i = 0; i < 2; i++)
#pragma unroll
        for (int j = 0; j < 8; j++)
#pragma unroll
            for (int k = 0; k < 4; k++) d[i][j][k] = 0.f;

    // ---- mainloop
    issue(0, 0);
#pragma unroll 1
    for (int c = 0; c < NCH; ++c) {
        if (c + 1 < NCH) { issue(c + 1, (c + 1) & 1); CP_WAIT_1(); }
        else             { CP_WAIT_0(); }
        __syncthreads();
        const float* cur = smem + (c & 1) * STAGE_FLOATS;
        const float* Bs  = cur + 2048;
#pragma unroll
        for (int ks = 0; ks < 4; ks++) {
            const int gcol = ks * 2 + (tg >> 1);
            const int fo = (tg & 1) * 2;
            uint32_t af[2][4];
#pragma unroll
            for (int i = 0; i < 2; i++) {
                const int ra = wm * 32 + i * 16 + gid;
                const int rb = ra + 8;
                float2 lo = *(const float2*)(cur + ra * 32 + ((gcol ^ (ra & 7)) << 2) + fo);
                float2 hi = *(const float2*)(cur + rb * 32 + ((gcol ^ (rb & 7)) << 2) + fo);
                af[i][0] = __float_as_uint(lo.x);
                af[i][1] = __float_as_uint(hi.x);
                af[i][2] = __float_as_uint(lo.y);
                af[i][3] = __float_as_uint(hi.y);
            }
            uint32_t bf[8][2];
#pragma unroll
            for (int j = 0; j < 8; j++) {
                const int n0 = wn * 64 + j * 8 + gid;
                float2 v = *(const float2*)(Bs + n0 * 32 + ((gcol ^ (n0 & 7)) << 2) + fo);
                bf[j][0] = __float_as_uint(v.x);
                bf[j][1] = __float_as_uint(v.y);
            }
#pragma unroll
            for (int i = 0; i < 2; i++)
#pragma unroll
                for (int j = 0; j < 8; j++)
                    mma_tf32(d[i][j], af[i], bf[j]);
        }
        __syncthreads();
    }

    // ---- epilogue
    if (!FUSED) {
#pragma unroll
        for (int i = 0; i < 2; i++) {
            const int r0 = mBase + wm * 32 + i * 16 + gid;
#pragma unroll
            for (int j = 0; j < 8; j++) {
                const int col = wn * 64 + j * 8 + tg * 2;
                *(float2*)(Z + (size_t)r0 * 256 + col)       = make_float2(d[i][j][0], d[i][j][1]);
                *(float2*)(Z + (size_t)(r0 + 8) * 256 + col) = make_float2(d[i][j][2], d[i][j][3]);
            }
        }
    } else {
        float* zs = smem;   // 64 rows x 258 floats (reuses staging; post-barrier)
#pragma unroll
        for (int i = 0; i < 2; i++) {
            const int r0 = wm * 32 + i * 16 + gid;
#pragma unroll
            for (int j = 0; j < 8; j++) {
                const int col = wn * 64 + j * 8 + tg * 2;
                *(float2*)(zs + r0 * 258 + col)       = make_float2(d[i][j][0], d[i][j][1]);
                *(float2*)(zs + (r0 + 8) * 258 + col) = make_float2(d[i][j][2], d[i][j][3]);
            }
        }
        __syncthreads();
#pragma unroll
        for (int it = 0; it < 16; it++) {
            const int idx = it * 256 + t;
            const int p = idx >> 6, f = idx & 63;
            const int m = mBase + p;
            const int b = m >> 12, pix = m & 4095;
            const size_t nrow = (size_t)(b * 16 + tstep) * 4096 + pix;
            const float* zr = zs + p * 258;
            const float* xr = xz + nrow * 256;
            const float zi = zr[f]       + xr[f]       + s_bias[f];
            const float zf = zr[64 + f]  + xr[64 + f]  + s_bias[64 + f];
            const float zg = zr[128 + f] + xr[128 + f] + s_bias[128 + f];
            const float zo = zr[192 + f] + xr[192 + f] + s_bias[192 + f];
            const float ig = hsig(zi), fg = hsig(zf), og = hsig(zo);
            const float cv = fg * cbuf[(size_t)m * 64 + f] + ig * tanhf(zg);
            const float hv = og * tanhf(cv);
            cbuf[(size_t)m * 64 + f] = cv;
            hp_out[(size_t)m * 64 + perm_dst(f)] = __uint_as_float(f2tf32(hv));
            out[nrow * 64 + f] = (hv - s_mm[f]) * s_scale[f] + s_beta[f];
        }
    }
}

// ================= launch ====================================================
extern "C" void kernel_launch(void* const* d_in, const int* in_sizes, int n_in,
                              void* d_out, int out_size) {
    const float* x     = (const float*)d_in[0];
    const float* W     = (const float*)d_in[1];
    const float* U     = (const float*)d_in[2];
    const float* bias  = (const float*)d_in[3];
    const float* gamma = (const float*)d_in[4];
    const float* beta  = (const float*)d_in[5];
    const float* mmean = (const float*)d_in[6];
    const float* mvar  = (const float*)d_in[7];
    float* out = (float*)d_out;

    float *xz_p, *xp_p, *hp0, *hp1, *c_p, *wt_p, *ut_p;
    cudaGetSymbolAddress((void**)&xz_p, g_xz);
    cudaGetSymbolAddress((void**)&xp_p, g_xp);
    cudaGetSymbolAddress((void**)&hp0,  g_hp0);
    cudaGetSymbolAddress((void**)&hp1,  g_hp1);
    cudaGetSymbolAddress((void**)&c_p,  g_c);
    cudaGetSymbolAddress((void**)&wt_p, g_Wt);
    cudaGetSymbolAddress((void**)&ut_p, g_Ut);

    cudaFuncSetAttribute(conv_mma<2, 0, 32, 128, 64, false>,
                         cudaFuncAttributeMaxDynamicSharedMemorySize, SMEM_BYTES);
    cudaFuncSetAttribute(conv_mma<1, 1, 64, 64, 64, true>,
                         cudaFuncAttributeMaxDynamicSharedMemorySize, SMEM_BYTES);

    const int stateN = 4 * 4096 * 64;
    zero_state_kernel<<<stateN / 256, 256>>>(hp0, c_p, stateN);

    const int xN = 64 * 16384 * 32;
    convert_x_kernel<<<xN / 512, 512>>>(x, xp_p, xN);
    transpose_w_kernel<<<(9 * 8192 + 255) / 256, 256>>>(W, wt_p, 9 * 8192);
    transpose_w_kernel<<<(18 * 8192 + 255) / 256, 256>>>(U, ut_p, 18 * 8192);

    // input-to-gate conv: all 64 images (M = 262144 -> 4096 CTAs)
    conv_mma<2, 0, 32, 128, 64, false><<<4096, 256, SMEM_BYTES>>>(
        xp_p, wt_p, xz_p, 0, nullptr, nullptr, nullptr, nullptr, nullptr, nullptr,
        nullptr, nullptr, nullptr);

    // recurrent loop with fused LSTM/BN epilogue (M = 16384 -> 256 CTAs, 1 wave @occ2)
    float* hin = hp0;
    float* hout = hp1;
    for (int t = 0; t < 16; ++t) {
        conv_mma<1, 1, 64, 64, 64, true><<<256, 256, SMEM_BYTES>>>(
            hin, ut_p, nullptr, t, xz_p, bias, gamma, beta, mmean, mvar,
            hout, c_p, out);
        float* tmp = hin; hin = hout; hout = tmp;
    }
}

// round 17
// speedup vs baseline: 1.4376x; 1.4376x over previous
#include <cuda_runtime.h>
#include <cuda_fp16.h>
#include <math.h>
#include <stdint.h>

// ================= scratch (device globals; no allocations) =================
__device__ float  g_xz[(size_t)64 * 4096 * 256];    // input-conv gates fp32 (268 MB)
__device__ __half g_xp[(size_t)64 * 16384 * 32];    // x fp16, k-interleaved (67 MB)
__device__ __half g_hp0[(size_t)4 * 4096 * 64];     // h fp16 k-interleaved
__device__ __half g_hp1[(size_t)4 * 4096 * 64];
__device__ float  g_c [(size_t)4 * 4096 * 64];
__device__ __half g_Wt[(size_t)9  * 256 * 32];      // W fp16 chunk-major interleaved
__device__ __half g_Ut[(size_t)18 * 256 * 32];

// ================= helpers ==================================================
__device__ __forceinline__ uint32_t smem_u32(const void* p) {
    uint32_t a;
    asm("{ .reg .u64 t; cvta.to.shared.u64 t, %1; cvt.u32.u64 %0, t; }" : "=r"(a) : "l"(p));
    return a;
}
__device__ __forceinline__ void mma_f16(float* d, uint32_t a0, uint32_t a1,
                                        uint32_t a2, uint32_t a3,
                                        uint32_t b0, uint32_t b1) {
    asm volatile("mma.sync.aligned.m16n8k16.row.col.f32.f16.f16.f32 "
                 "{%0,%1,%2,%3}, {%4,%5,%6,%7}, {%8,%9}, {%0,%1,%2,%3};"
                 : "+f"(d[0]), "+f"(d[1]), "+f"(d[2]), "+f"(d[3])
                 : "r"(a0), "r"(a1), "r"(a2), "r"(a3), "r"(b0), "r"(b1));
}
#define CP_ASYNC8(dst, src, sz) \
    asm volatile("cp.async.ca.shared.global [%0], [%1], 8, %2;" \
                 :: "r"(dst), "l"(src), "r"(sz) : "memory")
#define CP_COMMIT()  asm volatile("cp.async.commit_group;" ::: "memory")
#define CP_WAIT_1()  asm volatile("cp.async.wait_group 1;" ::: "memory")
#define CP_WAIT_0()  asm volatile("cp.async.wait_group 0;" ::: "memory")

__device__ __forceinline__ float hsig(float x) {
    return fminf(fmaxf(0.2f * x + 0.5f, 0.f), 1.f);
}

// fp16 m16n8k16 k-interleave within a 16-block:
// position p holds source k: [k0,k1,k8,k9, k2,k3,k10,k11, k4,k5,k12,k13, k6,k7,k14,k15]
__device__ __host__ __forceinline__ int perm_src16(int p) {   // p in [0,16)
    return 2 * (p >> 2) + ((p & 2) ? 8 : 0) + (p & 1);
}
__device__ __forceinline__ int perm_dst16(int k) {            // inverse
    return (k < 8) ? (4 * (k >> 1) + (k & 1))
                   : (4 * ((k & 7) >> 1) + 2 + (k & 1));
}

// smem: 2 stages of 24576 B (A 128x32h @+0 = 8192 B, B 256x32h @+8192 = 16384 B)
static constexpr uint32_t STAGE_BYTES = 24576;
// epilogue needs 64x258 floats = 66048 B > 2 stages (49152) -> request the max
static constexpr uint32_t SMEM_BYTES = 66048;

// ================= prep kernels =============================================
__global__ void zero_state_kernel(__half* __restrict__ h, float* __restrict__ c, int n) {
    int i = blockIdx.x * blockDim.x + threadIdx.x;
    if (i < n) { h[i] = __float2half(0.f); c[i] = 0.f; }
}

__global__ void convert_x_kernel(const float* __restrict__ x, __half* __restrict__ xp, int total) {
    int idx = blockIdx.x * blockDim.x + threadIdx.x;
    if (idx >= total) return;
    int pix = idx >> 5, pos = idx & 31;
    int k = (pos & 16) + perm_src16(pos & 15);
    xp[idx] = __float2half(x[pix * 32 + k]);
}

// Wt[ch][co][pos] = fp16(Wsrc[(ch*32 + k(pos))*256 + co])
__global__ void transpose_w_kernel(const float* __restrict__ Wsrc, __half* __restrict__ Wt2, int total) {
    int idx = blockIdx.x * blockDim.x + threadIdx.x;
    if (idx >= total) return;
    int ch = idx >> 13;
    int r  = idx & 8191;
    int co = r >> 5, pos = r & 31;
    int k = (pos & 16) + perm_src16(pos & 15);
    Wt2[idx] = __float2half(Wsrc[(ch * 32 + k) * 256 + co]);
}

// ================= fp16 m16n8k16 implicit-GEMM conv (+ fused LSTM) ==========
// BM=128, BN=256, BK=32; 512 threads = 16 warps (4m x 4n), warp tile 32x64.
template<int STRIDE, int PAD, int CIN, int HIN, int HOUT, bool FUSED>
__global__ void __launch_bounds__(512, 1)
conv_mma(const __half* __restrict__ X, const __half* __restrict__ Wt2,
         float* __restrict__ Z, int tstep,
         const float* __restrict__ xz,
         const float* __restrict__ bias, const float* __restrict__ gamma,
         const float* __restrict__ beta, const float* __restrict__ mmean,
         const float* __restrict__ mvar,
         __half* __restrict__ hp_out, float* __restrict__ cbuf,
         float* __restrict__ out) {
    extern __shared__ char smem[];
    __shared__ float s_bias[256], s_scale[64], s_beta[64], s_mm[64];

    const int t = threadIdx.x;
    if (FUSED) {
        if (t < 256) s_bias[t] = bias[t];
        if (t < 64) {
            s_scale[t] = gamma[t] * rsqrtf(mvar[t] + 1e-3f);
            s_beta[t]  = beta[t];
            s_mm[t]    = mmean[t];
        }
    }

    const int wid = t >> 5, lane = t & 31;
    const int gid = lane >> 2, tg = lane & 3;
    const int wm = wid >> 2, wn = wid & 3;       // warp grid 4(m) x 4(n)
    const int mBase = blockIdx.x * 128;
    constexpr int NCH = 9 * CIN / 32;

    // ---- cp.async geometry: g = 8B group (4 halves), rows r0A and r0A+64
    const int g8 = t & 7;
    const int r0A = t >> 3;
    int nimg[2], oyv[2], oxv[2];
#pragma unroll
    for (int k = 0; k < 2; k++) {
        const int m = mBase + r0A + k * 64;
        nimg[k] = m / (HOUT * HOUT);
        const int rem = m % (HOUT * HOUT);
        oyv[k] = rem / HOUT; oxv[k] = rem % HOUT;
    }
    const uint32_t sbase = smem_u32(smem);
    uint32_t aDst[2], bDst[4];
#pragma unroll
    for (int k = 0; k < 2; k++) {
        const int r = r0A + k * 64;
        aDst[k] = sbase + r * 64 + ((g8 ^ (r & 7)) << 3);
    }
#pragma unroll
    for (int k = 0; k < 4; k++) {
        const int co = (t >> 3) + k * 64;
        bDst[k] = sbase + 8192 + co * 64 + ((g8 ^ (co & 7)) << 3);
    }

    auto issue = [&](int c, int s) {
        const int tap   = (c * 32) / CIN;
        const int ciOff = (c * 32) % CIN;
        const int ky = tap / 3, kx = tap % 3;
        const uint32_t so = (uint32_t)s * STAGE_BYTES;
#pragma unroll
        for (int k = 0; k < 2; k++) {
            const int iy = oyv[k] * STRIDE + ky - PAD;
            const int ix = oxv[k] * STRIDE + kx - PAD;
            const bool ok = (iy >= 0) & (iy < HIN) & (ix >= 0) & (ix < HIN);
            const __half* src = ok
                ? X + (((size_t)nimg[k] * HIN + iy) * HIN + ix) * CIN + ciOff + g8 * 4
                : X;
            CP_ASYNC8(aDst[k] + so, src, ok ? 8 : 0);
        }
        const __half* bsrc = Wt2 + (size_t)c * 8192 + (t >> 3) * 32 + g8 * 4;
#pragma unroll
        for (int k = 0; k < 4; k++)
            CP_ASYNC8(bDst[k] + so, bsrc + k * 2048, 8);
        CP_COMMIT();
    };

    float d[2][8][4];
#pragma unroll
    for (int i = 0; i < 2; i++)
#pragma unroll
        for (int j = 0; j < 8; j++)
#pragma unroll
            for (int k = 0; k < 4; k++) d[i][j][k] = 0.f;

    // ---- mainloop
    issue(0, 0);
#pragma unroll 1
    for (int c = 0; c < NCH; ++c) {
        if (c + 1 < NCH) { issue(c + 1, (c + 1) & 1); CP_WAIT_1(); }
        else             { CP_WAIT_0(); }
        __syncthreads();
        const char* cur = smem + (c & 1) * STAGE_BYTES;
        const char* Bs  = cur + 8192;
#pragma unroll
        for (int ks = 0; ks < 2; ks++) {      // 16 k per step
            const int g = ks * 4 + tg;
            uint32_t af[2][4];
#pragma unroll
            for (int i = 0; i < 2; i++) {
                const int ra = wm * 32 + i * 16 + gid;
                const int rb = ra + 8;
                uint2 lo = *(const uint2*)(cur + ra * 64 + ((g ^ (ra & 7)) << 3));
                uint2 hi = *(const uint2*)(cur + rb * 64 + ((g ^ (rb & 7)) << 3));
                af[i][0] = lo.x;   // (ra,   2tg..2tg+1)
                af[i][1] = hi.x;   // (ra+8, 2tg..2tg+1)
                af[i][2] = lo.y;   // (ra,   2tg+8..2tg+9)
                af[i][3] = hi.y;   // (ra+8, 2tg+8..2tg+9)
            }
            uint32_t bf[8][2];
#pragma unroll
            for (int j = 0; j < 8; j++) {
                const int n0 = wn * 64 + j * 8 + gid;
                uint2 v = *(const uint2*)(Bs + n0 * 64 + ((g ^ (n0 & 7)) << 3));
                bf[j][0] = v.x;
                bf[j][1] = v.y;
            }
#pragma unroll
            for (int i = 0; i < 2; i++)
#pragma unroll
                for (int j = 0; j < 8; j++)
                    mma_f16(d[i][j], af[i][0], af[i][1], af[i][2], af[i][3],
                            bf[j][0], bf[j][1]);
        }
        __syncthreads();
    }

    // ---- epilogue
    if (!FUSED) {
#pragma unroll
        for (int i = 0; i < 2; i++) {
            const int r0 = mBase + wm * 32 + i * 16 + gid;
#pragma unroll
            for (int j = 0; j < 8; j++) {
                const int col = wn * 64 + j * 8 + tg * 2;
                *(float2*)(Z + (size_t)r0 * 256 + col)       = make_float2(d[i][j][0], d[i][j][1]);
                *(float2*)(Z + (size_t)(r0 + 8) * 256 + col) = make_float2(d[i][j][2], d[i][j][3]);
            }
        }
    } else {
        float* zs = (float*)smem;   // 64 rows x 258 floats (post-barrier reuse)
#pragma unroll 1
        for (int half = 0; half < 2; half++) {
            __syncthreads();
            if ((wm >> 1) == half) {
#pragma unroll
                for (int i = 0; i < 2; i++) {
                    const int r0 = (wm & 1) * 32 + i * 16 + gid;
#pragma unroll
                    for (int j = 0; j < 8; j++) {
                        const int col = wn * 64 + j * 8 + tg * 2;
                        *(float2*)(zs + r0 * 258 + col)       = make_float2(d[i][j][0], d[i][j][1]);
                        *(float2*)(zs + (r0 + 8) * 258 + col) = make_float2(d[i][j][2], d[i][j][3]);
                    }
                }
            }
            __syncthreads();
#pragma unroll
            for (int it = 0; it < 8; it++) {
                const int idx = it * 512 + t;
                const int p = idx >> 6, f = idx & 63;
                const int m = mBase + half * 64 + p;
                const int b = m >> 12, pix = m & 4095;
                const size_t nrow = (size_t)(b * 16 + tstep) * 4096 + pix;
                const float* zr = zs + p * 258;
                const float* xr = xz + nrow * 256;
                const float zi = zr[f]       + xr[f]       + s_bias[f];
                const float zf = zr[64 + f]  + xr[64 + f]  + s_bias[64 + f];
                const float zg = zr[128 + f] + xr[128 + f] + s_bias[128 + f];
                const float zo = zr[192 + f] + xr[192 + f] + s_bias[192 + f];
                const float ig = hsig(zi), fg = hsig(zf), og = hsig(zo);
                const float cv = fg * cbuf[(size_t)m * 64 + f] + ig * tanhf(zg);
                const float hv = og * tanhf(cv);
                cbuf[(size_t)m * 64 + f] = cv;
                const int hpos = (f & 48) + perm_dst16(f & 15);
                hp_out[(size_t)m * 64 + hpos] = __float2half(hv);
                out[nrow * 64 + f] = (hv - s_mm[f]) * s_scale[f] + s_beta[f];
            }
        }
    }
}

// ================= launch ====================================================
extern "C" void kernel_launch(void* const* d_in, const int* in_sizes, int n_in,
                              void* d_out, int out_size) {
    const float* x     = (const float*)d_in[0];
    const float* W     = (const float*)d_in[1];
    const float* U     = (const float*)d_in[2];
    const float* bias  = (const float*)d_in[3];
    const float* gamma = (const float*)d_in[4];
    const float* beta  = (const float*)d_in[5];
    const float* mmean = (const float*)d_in[6];
    const float* mvar  = (const float*)d_in[7];
    float* out = (float*)d_out;

    float *xz_p, *c_p;
    __half *xp_p, *hp0, *hp1, *wt_p, *ut_p;
    cudaGetSymbolAddress((void**)&xz_p, g_xz);
    cudaGetSymbolAddress((void**)&xp_p, g_xp);
    cudaGetSymbolAddress((void**)&hp0,  g_hp0);
    cudaGetSymbolAddress((void**)&hp1,  g_hp1);
    cudaGetSymbolAddress((void**)&c_p,  g_c);
    cudaGetSymbolAddress((void**)&wt_p, g_Wt);
    cudaGetSymbolAddress((void**)&ut_p, g_Ut);

    cudaFuncSetAttribute(conv_mma<2, 0, 32, 128, 64, false>,
                         cudaFuncAttributeMaxDynamicSharedMemorySize, SMEM_BYTES);
    cudaFuncSetAttribute(conv_mma<1, 1, 64, 64, 64, true>,
                         cudaFuncAttributeMaxDynamicSharedMemorySize, SMEM_BYTES);

    const int stateN = 4 * 4096 * 64;
    zero_state_kernel<<<stateN / 256, 256>>>(hp0, c_p, stateN);

    const int xN = 64 * 16384 * 32;
    convert_x_kernel<<<xN / 512, 512>>>(x, xp_p, xN);
    transpose_w_kernel<<<(9 * 8192 + 255) / 256, 256>>>(W, wt_p, 9 * 8192);
    transpose_w_kernel<<<(18 * 8192 + 255) / 256, 256>>>(U, ut_p, 18 * 8192);

    // input-to-gate conv: all 64 images (M = 262144 -> 2048 CTAs)
    conv_mma<2, 0, 32, 128, 64, false><<<2048, 512, SMEM_BYTES>>>(
        xp_p, wt_p, xz_p, 0, nullptr, nullptr, nullptr, nullptr, nullptr, nullptr,
        nullptr, nullptr, nullptr);

    // recurrent loop with fused LSTM/BN epilogue (M = 16384 -> 128 CTAs)
    __half* hin = hp0;
    __half* hout = hp1;
    for (int t = 0; t < 16; ++t) {
        conv_mma<1, 1, 64, 64, 64, true><<<128, 512, SMEM_BYTES>>>(
            hin, ut_p, nullptr, t, xz_p, bias, gamma, beta, mmean, mvar,
            hout, c_p, out);
        __half* tmp = hin; hin = hout; hout = tmp;
    }
}